// round 9
// baseline (speedup 1.0000x reference)
#include <cuda_runtime.h>
#include <cuda_bf16.h>

#define B_  16
#define N_  512
#define E_  32
#define HD  64

// Scratch: A[b][k][n] = H[b,n,:] @ W1[:32, k]
//          Bm[b][k][n] = H[b,n,:] @ W1[32:, k] + b1[k]
__device__ float g_A[B_ * HD * N_];
__device__ float g_Bm[B_ * HD * N_];

// ---------------------------------------------------------------------------
// Kernel 1: precompute A and Bm, k-major. 512 blocks (vs 256) for 2x SM
// coverage: blockIdx = khalf(2) x which(2) x nChunk(8) x b(16).
// ---------------------------------------------------------------------------
__global__ void __launch_bounds__(256) precompute_kernel(
    const float* __restrict__ H,
    const float* __restrict__ W1,
    const float* __restrict__ b1)
{
    int khalf  = blockIdx.x & 1;          // 0: k 0..31, 1: k 32..63
    int which  = (blockIdx.x >> 1) & 1;   // 0: A, 1: Bm
    int nChunk = (blockIdx.x >> 2) & 7;
    int b      = blockIdx.x >> 5;

    __shared__ float sW[E_ * 32];         // 32x32 quarter of W1
    __shared__ float sH[64 * 33];

    int tid = threadIdx.x;
    // W1 rows [which*32 .. +32), cols [khalf*32 .. +32)
    const float* Wsrc = W1 + which * E_ * HD + khalf * 32;
    #pragma unroll
    for (int p = tid; p < E_ * 32; p += 256) {
        int r = p >> 5, c = p & 31;
        sW[p] = Wsrc[r * HD + c];
    }

    int nBase = b * N_ + nChunk * 64;
    #pragma unroll
    for (int p = tid; p < 64 * E_; p += 256) {
        int r = p >> 5, c = p & 31;
        sH[r * 33 + c] = H[nBase * E_ + p];
    }
    __syncthreads();

    int nL    = tid & 63;
    int kOff  = (tid >> 6) * 8;           // 4 groups x 8 k each (of this half)

    float h[E_];
    #pragma unroll
    for (int e = 0; e < E_; e++) h[e] = sH[nL * 33 + e];

    float* dst = which ? g_Bm : g_A;
    #pragma unroll
    for (int kk = 0; kk < 8; kk++) {
        int kq = kOff + kk;               // 0..31 within half
        int k  = khalf * 32 + kq;         // global k
        float acc = which ? b1[k] : 0.0f;
        #pragma unroll
        for (int e = 0; e < E_; e++)
            acc = fmaf(h[e], sW[e * 32 + kq], acc);
        dst[(b * HD + k) * N_ + nChunk * 64 + nL] = acc;
    }

    cudaTriggerProgrammaticLaunchCompletion();
}

// ---------------------------------------------------------------------------
// packed f32x2 inner step (R2-proven fastest form)
// ---------------------------------------------------------------------------
__device__ __forceinline__ void pair_step(unsigned long long& acc,
                                          unsigned long long a2,
                                          unsigned long long b2,
                                          unsigned long long w2)
{
    asm("{\n\t"
        ".reg .f32 lo, hi;\n\t"
        ".reg .b64 t, r;\n\t"
        "add.rn.f32x2 t, %1, %2;\n\t"
        "mov.b64 {lo, hi}, t;\n\t"
        "max.f32 lo, lo, 0f00000000;\n\t"
        "max.f32 hi, hi, 0f00000000;\n\t"
        "mov.b64 r, {lo, hi};\n\t"
        "fma.rn.f32x2 %0, r, %3, %0;\n\t"
        "}"
        : "+l"(acc) : "l"(a2), "l"(b2), "l"(w2));
}

__device__ __forceinline__ unsigned long long dup_f32(float x)
{
    unsigned long long d;
    asm("mov.b64 %0, {%1, %1};" : "=l"(d) : "f"(x));
    return d;
}

// ---------------------------------------------------------------------------
// Kernel 2: EXACT R2 loop structure (fastest measured: 21.8us), plus PDL
// and param-passed weights (no memcpy graph nodes).
//   As_dup[k][i] : (a,a) duplicated -> broadcast LDS.64, no packing MOVs
//   Bs2[k][pos]  : natural (b_j,b_j+1) pairs, interleaved layout so both
//                  per-k reads are conflict-free stride-8B LDS.64
// ---------------------------------------------------------------------------
__global__ void __launch_bounds__(256) pair_kernel(
    const float* __restrict__ W2,
    const float* __restrict__ b2g,
    float* __restrict__ out)
{
    __shared__ alignas(16) unsigned long long As_dup[HD * 64];  // 32 KB
    __shared__ alignas(16) unsigned long long Bs2[HD * 32];     // 16 KB
    __shared__ unsigned long long sw2d[HD];
    __shared__ float sb2;

    int tid = threadIdx.x;

    // PDL-overlapped prolog (independent of precompute output)
    if (tid < HD) sw2d[tid] = dup_f32(W2[tid]);
    if (tid == 0) sb2 = b2g[0];

    int b = blockIdx.y;
    int t = blockIdx.x;
    int ti = 0;
    while (t >= (8 - ti)) { t -= (8 - ti); ti++; }
    int tj = ti + t;    // ti <= tj

    cudaGridDependencySynchronize();

    // Fill As_dup: each element duplicated (a,a)
    const float* Ag = g_A + (size_t)b * HD * N_ + ti * 64;
    #pragma unroll
    for (int p = 0; p < 16; p++) {
        int idx = tid + p * 256;          // 0..4095
        int k = idx >> 6, i = idx & 63;
        As_dup[idx] = dup_f32(Ag[k * N_ + i]);
    }

    // Fill Bs2: natural adjacent-j pairs, interleaved: pair jp -> (jp&1)*16 + jp>>1
    const float2* Bg = reinterpret_cast<const float2*>(g_Bm + (size_t)b * HD * N_ + tj * 64);
    #pragma unroll
    for (int p = 0; p < 8; p++) {
        int idx = tid + p * 256;          // 0..2047
        int k = idx >> 5, jp = idx & 31;
        float2 v = Bg[k * (N_ / 2) + jp];
        int pos = ((jp & 1) << 4) | (jp >> 1);
        Bs2[(k << 5) + pos] = *reinterpret_cast<unsigned long long*>(&v);
    }
    __syncthreads();

    int ty = tid >> 4, tx = tid & 15;

    unsigned long long acc[4][2];
    {
        unsigned long long bi = dup_f32(sb2);
        #pragma unroll
        for (int r = 0; r < 4; r++) { acc[r][0] = bi; acc[r][1] = bi; }
    }

    #pragma unroll 8
    for (int k = 0; k < HD; k++) {
        unsigned long long w2 = sw2d[k];                   // LDS.64 bcast
        unsigned long long b0  = Bs2[(k << 5) + tx];       // cols (4tx, 4tx+1)
        unsigned long long b1v = Bs2[(k << 5) + 16 + tx];  // cols (4tx+2, 4tx+3)
        const unsigned long long* Ak = &As_dup[(k << 6) + (ty << 2)];
        #pragma unroll
        for (int r = 0; r < 4; r++) {
            unsigned long long a2 = Ak[r];
            pair_step(acc[r][0], a2, b0, w2);
            pair_step(acc[r][1], a2, b1v, w2);
        }
    }

    // sigmoid epilogue
    float p[4][4];
    #pragma unroll
    for (int r = 0; r < 4; r++)
        #pragma unroll
        for (int cp = 0; cp < 2; cp++) {
            float lo, hi;
            asm("mov.b64 {%0, %1}, %2;" : "=f"(lo), "=f"(hi) : "l"(acc[r][cp]));
            p[r][cp * 2 + 0] = 1.0f / (1.0f + __expf(-lo));
            p[r][cp * 2 + 1] = 1.0f / (1.0f + __expf(-hi));
        }

    int i0 = ti * 64 + ty * 4;
    int j0 = tj * 64 + tx * 4;
    float* outb = out + (size_t)b * N_ * N_;

    if (ti != tj) {
        #pragma unroll
        for (int r = 0; r < 4; r++) {
            float4 v = make_float4(p[r][0], p[r][1], p[r][2], p[r][3]);
            *reinterpret_cast<float4*>(outb + (size_t)(i0 + r) * N_ + j0) = v;
        }
        #pragma unroll
        for (int c = 0; c < 4; c++) {
            float4 v = make_float4(p[0][c], p[1][c], p[2][c], p[3][c]);
            *reinterpret_cast<float4*>(outb + (size_t)(j0 + c) * N_ + i0) = v;
        }
    } else {
        #pragma unroll
        for (int r = 0; r < 4; r++)
            #pragma unroll
            for (int c = 0; c < 4; c++) {
                int i = i0 + r, j = j0 + c;
                if (i < j) {
                    float v = p[r][c];
                    outb[(size_t)i * N_ + j] = v;
                    outb[(size_t)j * N_ + i] = v;
                } else if (i == j) {
                    outb[(size_t)i * N_ + j] = 0.0f;
                }
            }
    }
}

extern "C" void kernel_launch(void* const* d_in, const int* in_sizes, int n_in,
                              void* d_out, int out_size)
{
    const float* H  = (const float*)d_in[0];   // node_emb [8192, 32]
    const float* W1 = (const float*)d_in[1];   // [64, 64]
    const float* b1 = (const float*)d_in[2];   // [64]
    const float* W2 = (const float*)d_in[3];   // [64]
    const float* b2 = (const float*)d_in[4];   // [1]
    float* out = (float*)d_out;                // [16, 512, 512]

    precompute_kernel<<<512, 256>>>(H, W1, b1);

    // PDL launch: pair_kernel prolog overlaps precompute tail + launch gap
    cudaLaunchConfig_t cfg = {};
    cfg.gridDim  = dim3(36, 16, 1);
    cfg.blockDim = dim3(256, 1, 1);
    cfg.dynamicSmemBytes = 0;
    cfg.stream = 0;
    cudaLaunchAttribute attrs[1];
    attrs[0].id = cudaLaunchAttributeProgrammaticStreamSerialization;
    attrs[0].val.programmaticStreamSerializationAllowed = 1;
    cfg.attrs = attrs;
    cfg.numAttrs = 1;
    cudaLaunchKernelEx(&cfg, pair_kernel, W2, b2, out);
}